// round 15
// baseline (speedup 1.0000x reference)
#include <cuda_runtime.h>
#include <cstdint>

#define BATCH 8
#define NPTS  8192
#define NS    2048
#define KNBR  32
#define TB    512
#define PPT   16             // points per thread in FPS
#define NPAIR (PPT / 2)      // 8 packed pairs
#define NWARP (TB / 32)      // 16

typedef unsigned long long u64;

// scratch: centroids padded to float4 for single STG.128 publish
__device__ float    g_new_xyz[BATCH * NS * 4];
__device__ unsigned g_progress[BATCH];

__device__ __forceinline__ unsigned ld_acq(const unsigned* p) {
    unsigned v;
    asm volatile("ld.acquire.gpu.global.u32 %0, [%1];" : "=r"(v) : "l"(p) : "memory");
    return v;
}
__device__ __forceinline__ void st_rel(unsigned* p, unsigned v) {
    asm volatile("st.release.gpu.global.u32 [%0], %1;" :: "l"(p), "r"(v) : "memory");
}

// packed f32x2 helpers (two independent IEEE f32 ops per instruction)
__device__ __forceinline__ u64 pk2(float lo, float hi) {
    u64 r;
    asm("mov.b64 %0, {%1, %2};" : "=l"(r) : "f"(lo), "f"(hi));
    return r;
}
__device__ __forceinline__ u64 add2(u64 a, u64 b) {
    u64 r;
    asm("add.rn.f32x2 %0, %1, %2;" : "=l"(r) : "l"(a), "l"(b));
    return r;
}
__device__ __forceinline__ u64 mul2(u64 a, u64 b) {
    u64 r;
    asm("mul.rn.f32x2 %0, %1, %2;" : "=l"(r) : "l"(a), "l"(b));
    return r;
}

extern "C" __global__ void reset_kernel() {
    if (threadIdx.x < BATCH) g_progress[threadIdx.x] = 0;
}

// ---------------------------------------------------------------------------
// Fused kernel. Blocks 0..7: FPS producer (one per batch).
// Blocks 8..: 16 warps, each handling one centroid: ball query + MLP + pool.
// ---------------------------------------------------------------------------
extern "C" __global__ void __launch_bounds__(TB, 1)
fused_kernel(const float* __restrict__ xyz,
             const float* __restrict__ w1, const float* __restrict__ b1,
             const float* __restrict__ w2, const float* __restrict__ b2,
             const float* __restrict__ w3, const float* __restrict__ b3,
             float* __restrict__ out)
{
    extern __shared__ float sm[];
    const int t    = threadIdx.x;
    const int lane = t & 31;
    const int w    = t >> 5;

    if (blockIdx.x < BATCH) {
        // ================= FPS producer =================
        __shared__ u64 skey2[2][32];    // [parity][warp or zero-pad]
        float* sx = sm;
        float* sy = sm + NPTS;
        float* sz = sm + 2 * NPTS;

        const int b = blockIdx.x;
        const float* base = xyz + (size_t)b * NPTS * 3;

        if (t < 64) {                   // zero the pad slots (lanes 16..31)
            int pp = t >> 5, ll = t & 31;
            if (ll >= NWARP) skey2[pp][ll] = 0ull;
        }

        for (int i = t; i < NPTS; i += TB) {
            sx[i] = base[i * 3 + 0];
            sy[i] = base[i * 3 + 1];
            sz[i] = base[i * 3 + 2];
        }
        __syncthreads();

        // pair p holds points idx = t + (2p)*TB (lo) and t + (2p+1)*TB (hi)
        // dd kept as int bit-patterns (all >= 0 -> int order == float order):
        // min/max/compare run on the ALU pipe (IMNMX/ISETP).
        u64 px2[NPAIR], py2[NPAIR], pz2[NPAIR];
        int ddlo[NPAIR], ddhi[NPAIR];
#pragma unroll
        for (int p = 0; p < NPAIR; p++) {
            int i0 = t + (2 * p) * TB;
            int i1 = t + (2 * p + 1) * TB;
            px2[p] = pk2(sx[i0], sx[i1]);
            py2[p] = pk2(sy[i0], sy[i1]);
            pz2[p] = pk2(sz[i0], sz[i1]);
            ddlo[p] = __float_as_int(1e10f);
            ddhi[p] = __float_as_int(1e10f);
        }

        int far = 0;
        float* out_xyz = out + (size_t)b * 3 * NS;
        float* gx4     = g_new_xyz + ((size_t)b * NS << 2);

        for (int s = 0; s < NS; s++) {
            const int par = s & 1;
            float cx = sx[far], cy = sy[far], cz = sz[far];
            // writer work split across two warps so no single warp is the
            // barrier straggler: warp 1 -> out planes, warp 0 -> consumer
            // centroid record + progress publish.
            if (w == 1 && lane < 3) {
                float val = (lane == 0) ? cx : (lane == 1) ? cy : cz;
                out_xyz[lane * NS + s] = val;
            }
            if (w == 0 && lane == 0) {
                float4 c4 = make_float4(cx, cy, cz, 0.0f);
                *(float4*)(gx4 + ((size_t)s << 2)) = c4;
                if ((s & 15) == 15)
                    st_rel(&g_progress[b], (unsigned)(s + 1));
            }
            // negation exact: a + (-c) == a - c
            u64 ncx = pk2(-cx, -cx);
            u64 ncy = pk2(-cy, -cy);
            u64 ncz = pk2(-cz, -cz);

            // distance update with in-loop leaf selects: each pair's
            // (value, slot) leaf is resolved immediately so only the depth-3
            // merge tree remains after the burst.
            int v0[NPAIR], i0[NPAIR];
#pragma unroll
            for (int p = 0; p < NPAIR; p++) {
                u64 dx = add2(px2[p], ncx);
                u64 dy = add2(py2[p], ncy);
                u64 dz = add2(pz2[p], ncz);
                dx = mul2(dx, dx);
                dy = mul2(dy, dy);
                dz = mul2(dz, dz);
                u64 d2 = add2(add2(dx, dy), dz);   // (x2+y2)+z2, exact order
                int dlo = (int)(unsigned)d2;
                int dhi = (int)(d2 >> 32);
                int nlo = (dlo < ddlo[p]) ? dlo : ddlo[p];   // IMNMX
                int nhi = (dhi < ddhi[p]) ? dhi : ddhi[p];   // IMNMX
                ddlo[p] = nlo;
                ddhi[p] = nhi;
                // hi wins only strictly (lo has the lower slot -> lower idx)
                v0[p] = (nhi > nlo) ? nhi : nlo;
                i0[p] = (nhi > nlo) ? (2 * p + 1) : (2 * p);
            }
            // depth-3 merge tree; ties keep the lower slot => lowest global
            // idx (idx = slot*TB + t is lex (slot, t) = numeric order).
#pragma unroll
            for (int stride = 1; stride < NPAIR; stride <<= 1) {
#pragma unroll
                for (int p = 0; p < NPAIR; p += 2 * stride) {
                    bool gt = (v0[p + stride] > v0[p]);   // right wins strictly
                    v0[p] = gt ? v0[p + stride] : v0[p];
                    i0[p] = gt ? i0[p + stride] : i0[p];
                }
            }
            int v  = v0[0];
            int mb = __reduce_max_sync(0xffffffffu, v);
            int myidx = (v == mb) ? (t + i0[0] * TB) : 0x7fffffff;
            int wi = __reduce_min_sync(0xffffffffu, myidx);
            if (lane == 0) {
                skey2[par][w] = ((u64)(unsigned)mb << 32) | (unsigned)(~wi);
            }
            __syncthreads();
            // combine all 16 warp winners (+16 zero pads) in every warp
            u64 kk = skey2[par][lane];
            int      hv = (int)(kk >> 32);
            unsigned lv = (unsigned)kk;
            int mB = __reduce_max_sync(0xffffffffu, hv);
            unsigned cand = (hv == mB) ? lv : 0u;
            unsigned mi = __reduce_max_sync(0xffffffffu, cand);
            far = (int)(~mi);
        }
        if (t == 0) st_rel(&g_progress[b], (unsigned)NS);
    } else {
        // ================= MLP consumer =================
        float* w1s = sm;              // 64x3
        float* b1s = w1s + 192;       // 64
        float* w2t = b1s + 64;        // 64x64 transposed [c][o]
        float* b2s = w2t + 4096;      // 64
        float* w3s = b2s + 64;        // 128x64 row-major [o][c]
        float* b3s = w3s + 8192;      // 128
        int*   lists = (int*)(b3s + 128);  // NWARP * 32

        for (int i = t; i < 192; i += TB) w1s[i] = w1[i];
        if (t < 64) { b1s[t] = b1[t]; b2s[t] = b2[t]; }
        for (int i = t; i < 4096; i += TB) {
            int o = i >> 6, c = i & 63;
            w2t[c * 64 + o] = w2[i];
        }
        for (int i = t; i < 8192; i += TB) w3s[i] = w3[i];
        if (t < 128) b3s[t] = b3[t];

        // block mapping: batch b, s range [sbase, sbase+16)
        const int idx   = blockIdx.x - BATCH;      // 0..1023
        const int b     = idx & 7;
        const int sbase = (idx >> 3) * NWARP;
        const int s     = sbase + w;

        // single poller per block, coarse gate on the whole block's range
        if (t == 0) {
            unsigned need = (unsigned)(sbase + NWARP);
            while (ld_acq(&g_progress[b]) < need) __nanosleep(2048);
        }
        __syncthreads();

        const float* xb   = xyz + (size_t)b * NPTS * 3;
        const float* cptr = g_new_xyz + (((size_t)b * NS + s) << 2);
        const float cx = cptr[0], cy = cptr[1], cz = cptr[2];

        // --- ball query: first KNBR points (ascending idx) with d2 <= r^2 ---
        int* list = lists + w * KNBR;
        int  cnt  = 0;
        for (int basei = 0; basei < NPTS; basei += 32) {
            int pi = basei + lane;
            float x = xb[pi * 3 + 0];
            float y = xb[pi * 3 + 1];
            float z = xb[pi * 3 + 2];
            float dx = __fsub_rn(x, cx);
            float dy = __fsub_rn(y, cy);
            float dz = __fsub_rn(z, cz);
            float d  = __fadd_rn(__fadd_rn(__fmul_rn(dx, dx), __fmul_rn(dy, dy)),
                                 __fmul_rn(dz, dz));
            bool within = (d <= 0.04f);
            unsigned m  = __ballot_sync(0xffffffffu, within);
            if (within) {
                int pos = cnt + __popc(m & ((1u << lane) - 1u));
                if (pos < KNBR) list[pos] = pi;
            }
            cnt += __popc(m);
            if (cnt >= KNBR) break;
        }
        __syncwarp();
        const int nb = list[(lane < cnt) ? lane : 0];

        const float rx = xb[nb * 3 + 0] - cx;
        const float ry = xb[nb * 3 + 1] - cy;
        const float rz = xb[nb * 3 + 2] - cz;

        // --- layer1 fused into layer2 accumulation ---
        float h2[64];
#pragma unroll
        for (int o = 0; o < 64; o++) h2[o] = b2s[o];

        for (int c = 0; c < 64; c++) {
            float a = fmaf(rx, w1s[c * 3 + 0], b1s[c]);
            a = fmaf(ry, w1s[c * 3 + 1], a);
            a = fmaf(rz, w1s[c * 3 + 2], a);
            float hv = fmaxf(a, 0.0f);
            const float4* row = (const float4*)(w2t + c * 64);
#pragma unroll
            for (int o4 = 0; o4 < 16; o4++) {
                float4 wv = row[o4];
                h2[o4 * 4 + 0] = fmaf(hv, wv.x, h2[o4 * 4 + 0]);
                h2[o4 * 4 + 1] = fmaf(hv, wv.y, h2[o4 * 4 + 1]);
                h2[o4 * 4 + 2] = fmaf(hv, wv.z, h2[o4 * 4 + 2]);
                h2[o4 * 4 + 3] = fmaf(hv, wv.w, h2[o4 * 4 + 3]);
            }
        }
#pragma unroll
        for (int o = 0; o < 64; o++) h2[o] = fmaxf(h2[o], 0.0f);

        // --- layer3 + relu + warp max-pool ---
        float* outb = out + (size_t)BATCH * 3 * NS + (size_t)b * 128 * NS + s;
        for (int o = 0; o < 128; o++) {
            float a = b3s[o];
            const float4* row = (const float4*)(w3s + o * 64);
#pragma unroll
            for (int c4 = 0; c4 < 16; c4++) {
                float4 wv = row[c4];
                a = fmaf(h2[c4 * 4 + 0], wv.x, a);
                a = fmaf(h2[c4 * 4 + 1], wv.y, a);
                a = fmaf(h2[c4 * 4 + 2], wv.z, a);
                a = fmaf(h2[c4 * 4 + 3], wv.w, a);
            }
            a = fmaxf(a, 0.0f);
#pragma unroll
            for (int off = 16; off; off >>= 1)
                a = fmaxf(a, __shfl_xor_sync(0xffffffffu, a, off));
            if (lane == 0) outb[(size_t)o * NS] = a;
        }
    }
}

// ---------------------------------------------------------------------------
extern "C" void kernel_launch(void* const* d_in, const int* in_sizes, int n_in,
                              void* d_out, int out_size)
{
    const float* xyz = (const float*)d_in[0];
    const float* w1 = (const float*)d_in[2];
    const float* b1 = (const float*)d_in[3];
    const float* w2 = (const float*)d_in[4];
    const float* b2 = (const float*)d_in[5];
    const float* w3 = (const float*)d_in[6];
    const float* b3 = (const float*)d_in[7];

    float* out = (float*)d_out;

    const int smem = 3 * NPTS * sizeof(float);   // 96 KB
    cudaFuncSetAttribute(fused_kernel,
                         cudaFuncAttributeMaxDynamicSharedMemorySize, smem);

    const int nmlp = (BATCH * NS) / NWARP;       // 1024 consumer blocks
    reset_kernel<<<1, 32>>>();
    fused_kernel<<<BATCH + nmlp, TB, smem>>>(xyz, w1, b1, w2, b2, w3, b3, out);
}